// round 1
// baseline (speedup 1.0000x reference)
#include <cuda_runtime.h>
#include <cuda_bf16.h>
#include <cstdint>
#include <cfloat>
#include <math.h>

#define B_  16
#define D_  256
#define T_  4096
#define N_  65536                  // B_*T_
#define K_  1024
#define Z_  16777216               // N_*D_

#define LDX   264                  // padded smem row, bf16 elems (528B: conflict-free frag loads)
#define LDX32 132
#define CH    64                   // codewords per chunk
#define NCHUNK (K_/CH)

// ---------------- scratch (static device memory; no runtime allocs) -------------
__device__ __align__(16) float g_Xf[N_ * D_];                 // 64MB: exact fp32 transposed inputs [n, d]
__device__ __align__(16) float g_scores[(size_t)N_ * K_];     // 256MB: approx scores
__device__ float g_e2[K_];
__device__ int   g_qidx[N_];
__device__ float g_qd2[N_];
__device__ int   g_counts[K_];

// ---------------- helpers ----------------
__device__ __forceinline__ uint32_t packbf2(float a, float b) {
    __nv_bfloat162 h = __floats2bfloat162_rn(a, b);           // .x = a (low), .y = b (high)
    return *reinterpret_cast<uint32_t*>(&h);
}

__device__ __forceinline__ void mma16816(float c[4],
                                         uint32_t a0, uint32_t a1, uint32_t a2, uint32_t a3,
                                         uint32_t b0, uint32_t b1) {
    asm volatile(
        "mma.sync.aligned.m16n8k16.row.col.f32.bf16.bf16.f32 "
        "{%0,%1,%2,%3}, {%4,%5,%6,%7}, {%8,%9}, {%0,%1,%2,%3};"
        : "+f"(c[0]), "+f"(c[1]), "+f"(c[2]), "+f"(c[3])
        : "r"(a0), "r"(a1), "r"(a2), "r"(a3), "r"(b0), "r"(b1));
}

// ---------------- kernels ----------------
__global__ void k_init() { g_counts[threadIdx.x] = 0; }

__global__ void k_e2(const float* __restrict__ embed) {
    int k = blockIdx.x * 8 + (threadIdx.x >> 5);
    int lane = threadIdx.x & 31;
    float s = 0.f;
    for (int d = lane; d < D_; d += 32) { float v = embed[(size_t)k * D_ + d]; s += v * v; }
    #pragma unroll
    for (int off = 16; off; off >>= 1) s += __shfl_xor_sync(0xffffffffu, s, off);
    if (lane == 0) g_e2[k] = s;
}

// inputs (B, D, T) -> g_Xf [(b*T + t), d]
__global__ void k_transpose(const float* __restrict__ in) {
    __shared__ float tile[32][33];
    int b = blockIdx.z, d0 = blockIdx.y * 32, t0 = blockIdx.x * 32;
    int tx = threadIdx.x, ty = threadIdx.y;
    const float* src = in + ((size_t)b * D_ + d0) * T_ + t0;
    #pragma unroll
    for (int i = 0; i < 4; i++) tile[ty + 8 * i][tx] = src[(size_t)(ty + 8 * i) * T_ + tx];
    __syncthreads();
    float* dst = g_Xf + ((size_t)b * T_ + t0) * D_ + d0;
    #pragma unroll
    for (int i = 0; i < 4; i++) dst[(size_t)(ty + 8 * i) * D_ + tx] = tile[tx][ty + 8 * i];
}

// Main: per CTA = 128 rows x all 1024 codewords. bf16 mma scores + running min,
// then exact fp32 refine on margin candidates.
__global__ void __launch_bounds__(256, 2) k_main(const float* __restrict__ embed) {
    extern __shared__ char sm[];
    __nv_bfloat16* Xs = (__nv_bfloat16*)sm;          // 128*LDX
    __nv_bfloat16* Es = Xs + 128 * LDX;              // 64*LDX
    float* e2s  = (float*)(Es + CH * LDX);           // 64
    float* sMin = e2s + CH;                          // 256 (2 n-warp groups x 128 rows)
    float* rowm = sMin + 256;                        // 128

    int tid = threadIdx.x;
    int Nbase = blockIdx.x * 128;

    // stage X tile (fp32 -> bf16, padded rows)
    {
        const float4* src = (const float4*)(g_Xf + (size_t)Nbase * D_);
        uint2* dst = (uint2*)Xs;
        #pragma unroll
        for (int i = 0; i < 32; i++) {
            int j = tid + i * 256;
            float4 v = src[j];
            int row = j >> 6, seg = j & 63;
            dst[row * 66 + seg] = make_uint2(packbf2(v.x, v.y), packbf2(v.z, v.w));
        }
    }

    int w = tid >> 5, lane = tid & 31, g = lane >> 2, tg = lane & 3;
    int wm = w & 3, wn = w >> 2;
    int mbase = wm * 32;

    float rmin[4] = {FLT_MAX, FLT_MAX, FLT_MAX, FLT_MAX};

    const uint32_t* Xs32 = (const uint32_t*)Xs;
    const uint32_t* Es32 = (const uint32_t*)Es;

    __syncthreads();

    for (int c = 0; c < NCHUNK; c++) {
        // stage E chunk (fp32 -> bf16) + e2 chunk
        {
            const float4* src = (const float4*)(embed + (size_t)c * CH * D_);
            uint2* dst = (uint2*)Es;
            #pragma unroll
            for (int i = 0; i < 16; i++) {
                int j = tid + i * 256;
                float4 v = src[j];
                int row = j >> 6, seg = j & 63;
                dst[row * 66 + seg] = make_uint2(packbf2(v.x, v.y), packbf2(v.z, v.w));
            }
            if (tid < CH) e2s[tid] = g_e2[c * CH + tid];
        }
        __syncthreads();

        float acc[2][4][4];
        #pragma unroll
        for (int tm = 0; tm < 2; tm++)
            #pragma unroll
            for (int tn = 0; tn < 4; tn++)
                #pragma unroll
                for (int q = 0; q < 4; q++) acc[tm][tn][q] = 0.f;

        #pragma unroll
        for (int ks = 0; ks < 16; ks++) {
            int kh = ks * 8;
            uint32_t a[2][4], b[4][2];
            #pragma unroll
            for (int tm = 0; tm < 2; tm++) {
                int r = mbase + tm * 16 + g;
                a[tm][0] = Xs32[r * LDX32 + kh + tg];
                a[tm][1] = Xs32[(r + 8) * LDX32 + kh + tg];
                a[tm][2] = Xs32[r * LDX32 + kh + 4 + tg];
                a[tm][3] = Xs32[(r + 8) * LDX32 + kh + 4 + tg];
            }
            #pragma unroll
            for (int tn = 0; tn < 4; tn++) {
                int er = wn * 32 + tn * 8 + g;
                b[tn][0] = Es32[er * LDX32 + kh + tg];
                b[tn][1] = Es32[er * LDX32 + kh + 4 + tg];
            }
            #pragma unroll
            for (int tm = 0; tm < 2; tm++)
                #pragma unroll
                for (int tn = 0; tn < 4; tn++)
                    mma16816(acc[tm][tn], a[tm][0], a[tm][1], a[tm][2], a[tm][3],
                             b[tn][0], b[tn][1]);
        }

        // epilogue: score = e2 - 2*dot; store scores + running min
        #pragma unroll
        for (int tm = 0; tm < 2; tm++) {
            #pragma unroll
            for (int tn = 0; tn < 4; tn++) {
                int cl = wn * 32 + tn * 8 + tg * 2;
                int kk = c * CH + cl;
                float e20 = e2s[cl], e21 = e2s[cl + 1];
                float s00 = fmaf(-2.f, acc[tm][tn][0], e20);
                float s01 = fmaf(-2.f, acc[tm][tn][1], e21);
                float s10 = fmaf(-2.f, acc[tm][tn][2], e20);
                float s11 = fmaf(-2.f, acc[tm][tn][3], e21);
                int r0 = mbase + tm * 16 + g;
                size_t gr = (size_t)(Nbase + r0);
                *(float2*)(g_scores + gr * K_ + kk)       = make_float2(s00, s01);
                *(float2*)(g_scores + (gr + 8) * K_ + kk) = make_float2(s10, s11);
                int sl0 = tm * 2, sl1 = tm * 2 + 1;
                rmin[sl0] = fminf(rmin[sl0], fminf(s00, s01));
                rmin[sl1] = fminf(rmin[sl1], fminf(s10, s11));
            }
        }
        __syncthreads();
    }

    // reduce running mins: across quad (cols), then across the 2 n-warp groups
    #pragma unroll
    for (int s = 0; s < 4; s++) {
        float v = rmin[s];
        v = fminf(v, __shfl_xor_sync(0xffffffffu, v, 1));
        v = fminf(v, __shfl_xor_sync(0xffffffffu, v, 2));
        if (tg == 0) {
            int row = mbase + (s >> 1) * 16 + (s & 1) * 8 + g;
            sMin[wn * 128 + row] = v;
        }
    }
    __syncthreads();
    if (tid < 128) rowm[tid] = fminf(sMin[tid], sMin[128 + tid]);
    __syncthreads();

    // exact refine: warp w owns rows [w*16, w*16+16)
    const float MARGIN = 4.0f;
    for (int rr = 0; rr < 16; rr++) {
        int row = w * 16 + rr;
        size_t n = (size_t)Nbase + row;
        float thr = rowm[row] + MARGIN;
        const float*  srow = g_scores + n * K_;
        const float4* xr   = (const float4*)(g_Xf + n * D_);
        float bestd = FLT_MAX; int bestk = 0;
        for (int it = 0; it < 32; it++) {
            float s = srow[it * 32 + lane];
            unsigned mk = __ballot_sync(0xffffffffu, s <= thr);
            while (mk) {
                int j = __ffs(mk) - 1; mk &= mk - 1;
                int kc = it * 32 + j;
                const float4* er = (const float4*)(embed + (size_t)kc * D_);
                float part = 0.f;
                #pragma unroll
                for (int q = 0; q < 2; q++) {
                    float4 xv = xr[lane * 2 + q];
                    float4 ev = er[lane * 2 + q];
                    float e0 = xv.x - ev.x, e1 = xv.y - ev.y;
                    float e2d = xv.z - ev.z, e3 = xv.w - ev.w;
                    part += e0 * e0 + e1 * e1 + e2d * e2d + e3 * e3;
                }
                #pragma unroll
                for (int off = 16; off; off >>= 1)
                    part += __shfl_xor_sync(0xffffffffu, part, off);
                if (part < bestd) { bestd = part; bestk = kc; }   // ascending k => first min
            }
        }
        if (lane == 0) {
            g_qidx[n] = bestk;
            g_qd2[n]  = bestd;
            atomicAdd(&g_counts[bestk], 1);
        }
    }
}

// z_q gather back to (B, D, T), coalesced both sides via smem transpose tile
__global__ void k_gather(const float* __restrict__ embed, float* __restrict__ out, int out_size) {
    __shared__ int kk[32];
    __shared__ float tile[32][257];
    if (out_size < Z_) return;
    int b  = blockIdx.x >> 7;
    int t0 = (blockIdx.x & 127) << 5;
    int tid = threadIdx.x;
    if (tid < 32) kk[tid] = g_qidx[(b << 12) + t0 + tid];
    __syncthreads();
    int w = tid >> 5, lane = tid & 31;
    #pragma unroll
    for (int r = w; r < 32; r += 8) {
        const float4* er = (const float4*)(embed + (size_t)kk[r] * D_);
        float4 v0 = er[lane * 2], v1 = er[lane * 2 + 1];
        float* trow = &tile[r][lane * 8];
        trow[0] = v0.x; trow[1] = v0.y; trow[2] = v0.z; trow[3] = v0.w;
        trow[4] = v1.x; trow[5] = v1.y; trow[6] = v1.z; trow[7] = v1.w;
    }
    __syncthreads();
    int tt = tid & 31;
    int dh = tid >> 5;
    float* obase = out + ((size_t)b * D_) * T_ + t0 + tt;
    #pragma unroll
    for (int dp = 0; dp < 32; dp++) {
        int d = dp * 8 + dh;
        obase[(size_t)d * T_] = tile[tt][d];
    }
}

// scalars: loss, kldiv (constant), perplexity
__global__ void k_final(float* __restrict__ out, int out_size) {
    __shared__ float sh[1024], sd[1024];
    int tid = threadIdx.x;
    float p = (float)g_counts[tid] * (1.0f / 65536.0f);
    sh[tid] = -p * logf(p + 1e-10f);
    float ds = 0.f;
    #pragma unroll 8
    for (int i = 0; i < 64; i++) ds += g_qd2[tid + i * 1024];
    sd[tid] = ds;
    __syncthreads();
    for (int s = 512; s; s >>= 1) {
        if (tid < s) { sh[tid] += sh[tid + s]; sd[tid] += sd[tid + s]; }
        __syncthreads();
    }
    if (tid == 0 && out_size >= Z_ + 18) {
        out[Z_] = 1.25f * sd[0] * (1.0f / 16777216.0f);   // vq + 0.25*commitment (identical means)
        float kld = (float)(6.931471805599453 * 4096.0);  // log(1024) * T
        #pragma unroll
        for (int i = 0; i < 16; i++) out[Z_ + 1 + i] = kld;
        out[Z_ + 17] = expf(sh[0]);
    }
}

extern "C" void kernel_launch(void* const* d_in, const int* in_sizes, int n_in,
                              void* d_out, int out_size) {
    const float* inputs = (const float*)d_in[0];
    const float* embed  = (const float*)d_in[1];
    float* out = (float*)d_out;

    const int SMEM = 128 * LDX * 2 + CH * LDX * 2 + CH * 4 + 256 * 4 + 128 * 4; // 103168 B
    cudaFuncSetAttribute(k_main, cudaFuncAttributeMaxDynamicSharedMemorySize, SMEM);

    k_init<<<1, K_>>>();
    k_e2<<<K_ / 8, 256>>>(embed);
    k_transpose<<<dim3(T_ / 32, D_ / 32, B_), dim3(32, 8)>>>(inputs);
    k_main<<<N_ / 128, 256, SMEM>>>(embed);
    k_gather<<<(B_ * T_) / 32, 256>>>(embed, out, out_size);
    k_final<<<1, 1024>>>(out, out_size);
}

// round 2
// speedup vs baseline: 2.1127x; 2.1127x over previous
#include <cuda_runtime.h>
#include <cuda_bf16.h>
#include <cuda_fp16.h>
#include <cstdint>
#include <cfloat>
#include <math.h>

#define B_  16
#define D_  256
#define T_  4096
#define N_  65536                  // B_*T_
#define K_  1024
#define Z_  16777216               // N_*D_

#define CH      64                 // codewords per chunk
#define NCHUNK  (K_/CH)            // 16
#define LDB     528                // padded smem row stride in BYTES (33 x 16B, odd -> conflict-free ldmatrix)
#define CMAX    32                 // candidate list capacity per row
#define MARGIN  2.0f

// ---------------- scratch (static device memory) ----------------
__device__ __align__(16) float          g_Xf [N_ * D_];   // 64MB fp32 transposed inputs [n][d]
__device__ __align__(16) __nv_bfloat16  g_Xbf[N_ * D_];   // 32MB bf16 transposed inputs
__device__ __align__(16) __nv_bfloat16  g_Ebf[K_ * D_];   // 512KB bf16 codebook
__device__ __align__(16) float g_e2[K_];
__device__ int   g_qidx[N_];
__device__ float g_qd2[N_];
__device__ int   g_counts[K_];

// ---------------- helpers ----------------
__device__ __forceinline__ unsigned fkey(float f) {       // order-preserving float->uint
    unsigned u = __float_as_uint(f);
    return u ^ ((unsigned)((int)u >> 31) | 0x80000000u);
}
__device__ __forceinline__ float fdecode(unsigned u) {
    unsigned m = (u >> 31) ? 0x80000000u : 0xFFFFFFFFu;
    return __uint_as_float(u ^ m);
}
__device__ __forceinline__ void cp16(uint32_t dst, const void* src) {
    asm volatile("cp.async.cg.shared.global [%0], [%1], 16;" :: "r"(dst), "l"(src));
}
__device__ __forceinline__ void ldsm4(uint32_t r[4], uint32_t addr) {
    asm volatile("ldmatrix.sync.aligned.m8n8.x4.shared.b16 {%0,%1,%2,%3}, [%4];"
                 : "=r"(r[0]), "=r"(r[1]), "=r"(r[2]), "=r"(r[3]) : "r"(addr));
}
__device__ __forceinline__ void mma16816(float c[4], const uint32_t a[4],
                                         uint32_t b0, uint32_t b1) {
    asm volatile(
        "mma.sync.aligned.m16n8k16.row.col.f32.bf16.bf16.f32 "
        "{%0,%1,%2,%3}, {%4,%5,%6,%7}, {%8,%9}, {%0,%1,%2,%3};"
        : "+f"(c[0]), "+f"(c[1]), "+f"(c[2]), "+f"(c[3])
        : "r"(a[0]), "r"(a[1]), "r"(a[2]), "r"(a[3]), "r"(b0), "r"(b1));
}
// exact fp32 distance, warp-cooperative (identical arithmetic to round-1 pass)
__device__ __forceinline__ float dist2(float4 xv0, float4 xv1, const float* e, int lane) {
    const float4* er = (const float4*)e;
    float4 ev0 = er[lane * 2], ev1 = er[lane * 2 + 1];
    float d0 = xv0.x - ev0.x, d1 = xv0.y - ev0.y, d2 = xv0.z - ev0.z, d3 = xv0.w - ev0.w;
    float part = d0 * d0 + d1 * d1 + d2 * d2 + d3 * d3;
    d0 = xv1.x - ev1.x; d1 = xv1.y - ev1.y; d2 = xv1.z - ev1.z; d3 = xv1.w - ev1.w;
    part += d0 * d0 + d1 * d1 + d2 * d2 + d3 * d3;
    #pragma unroll
    for (int off = 16; off; off >>= 1) part += __shfl_xor_sync(0xffffffffu, part, off);
    return part;
}

// ---------------- small kernels ----------------
__global__ void k_init() { g_counts[threadIdx.x] = 0; }

__global__ void k_e2(const float* __restrict__ embed) {
    int k = blockIdx.x * 8 + (threadIdx.x >> 5);
    int lane = threadIdx.x & 31;
    float s = 0.f;
    for (int d = lane; d < D_; d += 32) { float v = embed[(size_t)k * D_ + d]; s += v * v; }
    #pragma unroll
    for (int off = 16; off; off >>= 1) s += __shfl_xor_sync(0xffffffffu, s, off);
    if (lane == 0) g_e2[k] = s;
}

__global__ void k_ebf(const float* __restrict__ embed) {
    int i = blockIdx.x * 256 + threadIdx.x;          // 256 blocks -> covers K_*D_/4
    float4 v = ((const float4*)embed)[i];
    __nv_bfloat162 lo = __floats2bfloat162_rn(v.x, v.y);
    __nv_bfloat162 hi = __floats2bfloat162_rn(v.z, v.w);
    uint2 p;
    p.x = *reinterpret_cast<uint32_t*>(&lo);
    p.y = *reinterpret_cast<uint32_t*>(&hi);
    ((uint2*)g_Ebf)[i] = p;
}

// inputs (B, D, T) -> g_Xf fp32 [n][d] + g_Xbf bf16 [n][d]
__global__ void k_transpose(const float* __restrict__ in) {
    __shared__ float tile[32][33];
    int b = blockIdx.z, d0 = blockIdx.y * 32, t0 = blockIdx.x * 32;
    int tx = threadIdx.x, ty = threadIdx.y;
    const float* src = in + ((size_t)b * D_ + d0) * T_ + t0;
    #pragma unroll
    for (int i = 0; i < 4; i++) tile[ty + 8 * i][tx] = src[(size_t)(ty + 8 * i) * T_ + tx];
    __syncthreads();
    float* dst = g_Xf + ((size_t)b * T_ + t0) * D_ + d0;
    #pragma unroll
    for (int i = 0; i < 4; i++) dst[(size_t)(ty + 8 * i) * D_ + tx] = tile[tx][ty + 8 * i];
    if (tx < 16) {
        #pragma unroll
        for (int i = 0; i < 4; i++) {
            int t = ty + 8 * i;
            __nv_bfloat162 h = __floats2bfloat162_rn(tile[2 * tx][t], tile[2 * tx + 1][t]);
            *reinterpret_cast<uint32_t*>(g_Xbf + ((size_t)(b * T_ + t0 + t)) * D_ + d0 + 2 * tx)
                = *reinterpret_cast<uint32_t*>(&h);
        }
    }
}

// ---------------- main: mma scores + online candidates + exact refine ----------------
__global__ void __launch_bounds__(256, 1) k_main(const float* __restrict__ embed) {
    extern __shared__ char sm[];
    char* Xs = sm;                                   // 128 rows x LDB
    char* Es = sm + 128 * LDB;                       // 2 x CH x LDB
    float*    e2s     = (float*)(sm + 128 * LDB + 2 * CH * LDB);   // 1024 floats
    unsigned* rowminU = (unsigned*)(e2s + K_);                     // 128
    int*      cnt     = (int*)(rowminU + 128);                     // 128
    unsigned* list    = (unsigned*)(cnt + 128);                    // 128*CMAX

    const int tid  = threadIdx.x;
    const int Nbase = blockIdx.x * 128;
    const int lane = tid & 31, w = tid >> 5;
    const int wm = w & 3, wn = w >> 2;
    const int g = lane >> 2, tg = lane & 3;

    const uint32_t XsA  = (uint32_t)__cvta_generic_to_shared(Xs);
    const uint32_t EsA0 = (uint32_t)__cvta_generic_to_shared(Es);
    const uint32_t EsA1 = EsA0 + CH * LDB;

    // ---- prologue: async X tile + E0 + E1 ----
    {
        const __nv_bfloat16* src = g_Xbf + (size_t)Nbase * D_;
        #pragma unroll
        for (int i = 0; i < 16; i++) {
            int j = tid + i * 256, row = j >> 5, u = j & 31;
            cp16(XsA + row * LDB + u * 16, src + (size_t)row * D_ + u * 8);
        }
        const __nv_bfloat16* es = g_Ebf;
        #pragma unroll
        for (int i = 0; i < 8; i++) {
            int j = tid + i * 256, row = j >> 5, u = j & 31;
            cp16(EsA0 + row * LDB + u * 16, es + (size_t)row * D_ + u * 8);
        }
        asm volatile("cp.async.commit_group;");
        es = g_Ebf + CH * D_;
        #pragma unroll
        for (int i = 0; i < 8; i++) {
            int j = tid + i * 256, row = j >> 5, u = j & 31;
            cp16(EsA1 + row * LDB + u * 16, es + (size_t)row * D_ + u * 8);
        }
        asm volatile("cp.async.commit_group;");
    }
    // e2 table + per-row state init (regular ops, overlap with cp.async)
    ((float4*)e2s)[tid] = ((const float4*)g_e2)[tid];
    if (tid < 128) { rowminU[tid] = 0xFFFFFFFFu; cnt[tid] = 0; }

    const uint32_t aAddr = XsA + (uint32_t)((wm * 32 + (lane & 15)) * LDB + (lane >> 4) * 16);
    const uint32_t bOff  = (uint32_t)((wn * 32 + (lane & 15)) * LDB + (lane >> 4) * 16);

    #pragma unroll 1
    for (int c = 0; c < NCHUNK; c++) {
        if (c == NCHUNK - 1) { asm volatile("cp.async.wait_group 0;" ::: "memory"); }
        else                 { asm volatile("cp.async.wait_group 1;" ::: "memory"); }
        __syncthreads();

        const uint32_t bAddr = ((c & 1) ? EsA1 : EsA0) + bOff;

        float acc[2][4][4];
        #pragma unroll
        for (int tm = 0; tm < 2; tm++)
            #pragma unroll
            for (int tn = 0; tn < 4; tn++)
                #pragma unroll
                for (int q = 0; q < 4; q++) acc[tm][tn][q] = 0.f;

        #pragma unroll
        for (int ks = 0; ks < 16; ks++) {
            uint32_t a0[4], a1[4], b0[4], b1[4];
            ldsm4(a0, aAddr + ks * 32);
            ldsm4(a1, aAddr + 16 * LDB + ks * 32);
            ldsm4(b0, bAddr + ks * 32);
            ldsm4(b1, bAddr + 16 * LDB + ks * 32);
            mma16816(acc[0][0], a0, b0[0], b0[2]);
            mma16816(acc[0][1], a0, b0[1], b0[3]);
            mma16816(acc[0][2], a0, b1[0], b1[2]);
            mma16816(acc[0][3], a0, b1[1], b1[3]);
            mma16816(acc[1][0], a1, b0[0], b0[2]);
            mma16816(acc[1][1], a1, b0[1], b0[3]);
            mma16816(acc[1][2], a1, b1[0], b1[2]);
            mma16816(acc[1][3], a1, b1[1], b1[3]);
        }

        // scores + running row-min
        float lmin[4] = {FLT_MAX, FLT_MAX, FLT_MAX, FLT_MAX};
        #pragma unroll
        for (int tm = 0; tm < 2; tm++) {
            #pragma unroll
            for (int tn = 0; tn < 4; tn++) {
                int kc = c * CH + wn * 32 + tn * 8 + tg * 2;
                float e20 = e2s[kc], e21 = e2s[kc + 1];
                acc[tm][tn][0] = fmaf(-2.f, acc[tm][tn][0], e20);
                acc[tm][tn][1] = fmaf(-2.f, acc[tm][tn][1], e21);
                acc[tm][tn][2] = fmaf(-2.f, acc[tm][tn][2], e20);
                acc[tm][tn][3] = fmaf(-2.f, acc[tm][tn][3], e21);
                lmin[tm * 2 + 0] = fminf(lmin[tm * 2 + 0], fminf(acc[tm][tn][0], acc[tm][tn][1]));
                lmin[tm * 2 + 1] = fminf(lmin[tm * 2 + 1], fminf(acc[tm][tn][2], acc[tm][tn][3]));
            }
        }
        #pragma unroll
        for (int s = 0; s < 4; s++) {
            float v = lmin[s];
            v = fminf(v, __shfl_xor_sync(0xffffffffu, v, 1));
            v = fminf(v, __shfl_xor_sync(0xffffffffu, v, 2));
            if (tg == 0) {
                int row = wm * 32 + (s >> 1) * 16 + (s & 1) * 8 + g;
                atomicMin(&rowminU[row], fkey(v));
            }
        }
        __syncthreads();

        // prefetch chunk c+2 into the buffer we just finished reading
        if (c + 2 < NCHUNK) {
            uint32_t dstA = (c & 1) ? EsA1 : EsA0;
            const __nv_bfloat16* es = g_Ebf + (size_t)(c + 2) * CH * D_;
            #pragma unroll
            for (int i = 0; i < 8; i++) {
                int j = tid + i * 256, row = j >> 5, u = j & 31;
                cp16(dstA + row * LDB + u * 16, es + (size_t)row * D_ + u * 8);
            }
            asm volatile("cp.async.commit_group;");
        }

        // candidate collection vs (current) row minima + MARGIN
        float thr[4];
        #pragma unroll
        for (int s = 0; s < 4; s++) {
            int row = wm * 32 + (s >> 1) * 16 + (s & 1) * 8 + g;
            thr[s] = fdecode(rowminU[row]) + MARGIN;
        }
        #pragma unroll
        for (int tm = 0; tm < 2; tm++)
            #pragma unroll
            for (int tn = 0; tn < 4; tn++)
                #pragma unroll
                for (int q = 0; q < 4; q++) {
                    float sc = acc[tm][tn][q];
                    int slot = tm * 2 + (q >> 1);
                    if (sc <= thr[slot]) {
                        int row = wm * 32 + tm * 16 + (q >> 1) * 8 + g;
                        int kk  = c * CH + wn * 32 + tn * 8 + tg * 2 + (q & 1);
                        int pos = atomicAdd(&cnt[row], 1);
                        if (pos < CMAX)
                            list[row * CMAX + pos] =
                                ((unsigned)kk << 16) |
                                (unsigned)__half_as_ushort(__float2half_rn(sc));
                    }
                }
    }
    __syncthreads();

    // ---- exact refine: warp w owns rows [w*16, w*16+16) ----
    for (int rr = 0; rr < 16; rr++) {
        int row = w * 16 + rr;
        size_t n = (size_t)Nbase + row;
        float rmn = fdecode(rowminU[row]);
        int c_ = cnt[row];
        const float4* xr = (const float4*)(g_Xf + n * D_);
        float4 xv0 = xr[lane * 2], xv1 = xr[lane * 2 + 1];
        float bestd = FLT_MAX; int bestk = 0;
        if (c_ <= CMAX) {
            float thr = rmn + MARGIN + 0.5f;   // + half-precision storage slack
            unsigned e = (lane < c_) ? list[row * CMAX + lane] : 0u;
            float sh = (lane < c_)
                ? __half2float(__ushort_as_half((unsigned short)(e & 0xFFFFu))) : FLT_MAX;
            unsigned mk = __ballot_sync(0xffffffffu, sh <= thr);
            while (mk) {
                int j = __ffs(mk) - 1; mk &= mk - 1;
                int kc = (int)(__shfl_sync(0xffffffffu, e, j) >> 16);
                float part = dist2(xv0, xv1, embed + (size_t)kc * D_, lane);
                if (part < bestd || (part == bestd && kc < bestk)) { bestd = part; bestk = kc; }
            }
        } else {
            // overflow fallback (statistically ~never): exact scan of all codewords
            for (int kc = 0; kc < K_; kc++) {
                float part = dist2(xv0, xv1, embed + (size_t)kc * D_, lane);
                if (part < bestd) { bestd = part; bestk = kc; }
            }
        }
        if (lane == 0) {
            g_qidx[n] = bestk;
            g_qd2[n]  = bestd;
            atomicAdd(&g_counts[bestk], 1);
        }
    }
}

// ---------------- z_q gather back to (B, D, T) ----------------
__global__ void k_gather(const float* __restrict__ embed, float* __restrict__ out, int out_size) {
    __shared__ int kk[32];
    __shared__ float tile[32][257];
    if (out_size < Z_) return;
    int b  = blockIdx.x >> 7;
    int t0 = (blockIdx.x & 127) << 5;
    int tid = threadIdx.x;
    if (tid < 32) kk[tid] = g_qidx[(b << 12) + t0 + tid];
    __syncthreads();
    int w = tid >> 5, lane = tid & 31;
    #pragma unroll
    for (int r = w; r < 32; r += 8) {
        const float4* er = (const float4*)(embed + (size_t)kk[r] * D_);
        float4 v0 = er[lane * 2], v1 = er[lane * 2 + 1];
        float* trow = &tile[r][lane * 8];
        trow[0] = v0.x; trow[1] = v0.y; trow[2] = v0.z; trow[3] = v0.w;
        trow[4] = v1.x; trow[5] = v1.y; trow[6] = v1.z; trow[7] = v1.w;
    }
    __syncthreads();
    int tt = tid & 31;
    int dh = tid >> 5;
    float* obase = out + ((size_t)b * D_) * T_ + t0 + tt;
    #pragma unroll
    for (int dp = 0; dp < 32; dp++) {
        int d = dp * 8 + dh;
        obase[(size_t)d * T_] = tile[tt][d];
    }
}

// ---------------- scalars: loss, kldiv (constant), perplexity ----------------
__global__ void k_final(float* __restrict__ out, int out_size) {
    __shared__ float sh[1024], sd[1024];
    int tid = threadIdx.x;
    float p = (float)g_counts[tid] * (1.0f / 65536.0f);
    sh[tid] = -p * logf(p + 1e-10f);
    float ds = 0.f;
    #pragma unroll 8
    for (int i = 0; i < 64; i++) ds += g_qd2[tid + i * 1024];
    sd[tid] = ds;
    __syncthreads();
    for (int s = 512; s; s >>= 1) {
        if (tid < s) { sh[tid] += sh[tid + s]; sd[tid] += sd[tid + s]; }
        __syncthreads();
    }
    if (tid == 0 && out_size >= Z_ + 18) {
        out[Z_] = 1.25f * sd[0] * (1.0f / 16777216.0f);
        float kld = (float)(6.931471805599453 * 4096.0);  // log(1024) * T
        #pragma unroll
        for (int i = 0; i < 16; i++) out[Z_ + 1 + i] = kld;
        out[Z_ + 17] = expf(sh[0]);
    }
}

extern "C" void kernel_launch(void* const* d_in, const int* in_sizes, int n_in,
                              void* d_out, int out_size) {
    const float* inputs = (const float*)d_in[0];
    const float* embed  = (const float*)d_in[1];
    float* out = (float*)d_out;

    const int SMEM = 128 * LDB + 2 * CH * LDB + K_ * 4 + 128 * 4 + 128 * 4 + 128 * CMAX * 4;
    cudaFuncSetAttribute(k_main, cudaFuncAttributeMaxDynamicSharedMemorySize, SMEM);

    k_init<<<1, K_>>>();
    k_e2<<<K_ / 8, 256>>>(embed);
    k_ebf<<<256, 256>>>(embed);
    k_transpose<<<dim3(T_ / 32, D_ / 32, B_), dim3(32, 8)>>>(inputs);
    k_main<<<N_ / 128, 256, SMEM>>>(embed);
    k_gather<<<(B_ * T_) / 32, 256>>>(embed, out, out_size);
    k_final<<<1, 1024>>>(out, out_size);
}

// round 3
// speedup vs baseline: 2.4458x; 1.1577x over previous
#include <cuda_runtime.h>
#include <cuda_bf16.h>
#include <cuda_fp16.h>
#include <cstdint>
#include <cfloat>
#include <math.h>

#define B_  16
#define D_  256
#define T_  4096
#define N_  65536                  // B_*T_
#define K_  1024
#define Z_  16777216               // N_*D_

#define CH      32                 // codewords per chunk
#define NCHUNK  (K_/CH)            // 32
#define LDB     528                // padded smem row stride in BYTES (33 x 16B, odd -> conflict-free ldmatrix)
#define CMAX    16                 // candidate list capacity per row
#define MARGIN  1.0f

// ---------------- scratch (static device memory) ----------------
__device__ __align__(16) float          g_Xf [N_ * D_];   // 64MB fp32 transposed inputs [n][d]
__device__ __align__(16) __nv_bfloat16  g_Xbf[N_ * D_];   // 32MB bf16 transposed inputs
__device__ __align__(16) __nv_bfloat16  g_Ebf[K_ * D_];   // 512KB bf16 codebook
__device__ __align__(16) float g_e2[K_];
__device__ int   g_qidx[N_];
__device__ float g_qd2[N_];
__device__ int   g_counts[K_];

// ---------------- helpers ----------------
__device__ __forceinline__ unsigned fkey(float f) {       // order-preserving float->uint
    unsigned u = __float_as_uint(f);
    return u ^ ((unsigned)((int)u >> 31) | 0x80000000u);
}
__device__ __forceinline__ float fdecode(unsigned u) {
    unsigned m = (u >> 31) ? 0x80000000u : 0xFFFFFFFFu;
    return __uint_as_float(u ^ m);
}
__device__ __forceinline__ void cp16(uint32_t dst, const void* src) {
    asm volatile("cp.async.cg.shared.global [%0], [%1], 16;" :: "r"(dst), "l"(src));
}
__device__ __forceinline__ void ldsm4(uint32_t r[4], uint32_t addr) {
    asm volatile("ldmatrix.sync.aligned.m8n8.x4.shared.b16 {%0,%1,%2,%3}, [%4];"
                 : "=r"(r[0]), "=r"(r[1]), "=r"(r[2]), "=r"(r[3]) : "r"(addr));
}
__device__ __forceinline__ void mma16816(float c[4], const uint32_t a[4],
                                         uint32_t b0, uint32_t b1) {
    asm volatile(
        "mma.sync.aligned.m16n8k16.row.col.f32.bf16.bf16.f32 "
        "{%0,%1,%2,%3}, {%4,%5,%6,%7}, {%8,%9}, {%0,%1,%2,%3};"
        : "+f"(c[0]), "+f"(c[1]), "+f"(c[2]), "+f"(c[3])
        : "r"(a[0]), "r"(a[1]), "r"(a[2]), "r"(a[3]), "r"(b0), "r"(b1));
}
// exact fp32 distance, warp-cooperative
__device__ __forceinline__ float dist2(float4 xv0, float4 xv1, const float* e, int lane) {
    const float4* er = (const float4*)e;
    float4 ev0 = er[lane * 2], ev1 = er[lane * 2 + 1];
    float d0 = xv0.x - ev0.x, d1 = xv0.y - ev0.y, d2 = xv0.z - ev0.z, d3 = xv0.w - ev0.w;
    float part = d0 * d0 + d1 * d1 + d2 * d2 + d3 * d3;
    d0 = xv1.x - ev1.x; d1 = xv1.y - ev1.y; d2 = xv1.z - ev1.z; d3 = xv1.w - ev1.w;
    part += d0 * d0 + d1 * d1 + d2 * d2 + d3 * d3;
    #pragma unroll
    for (int off = 16; off; off >>= 1) part += __shfl_xor_sync(0xffffffffu, part, off);
    return part;
}

// ---------------- prep: counts=0, bf16 codebook, e2 ----------------
__global__ void k_prep(const float* __restrict__ embed) {
    __shared__ float wsum[8];
    int tid = threadIdx.x;
    int i = blockIdx.x * 256 + tid;                  // float4 index over K_*D_/4 = 65536
    float4 v = ((const float4*)embed)[i];
    __nv_bfloat162 lo = __floats2bfloat162_rn(v.x, v.y);
    __nv_bfloat162 hi = __floats2bfloat162_rn(v.z, v.w);
    uint2 p;
    p.x = *reinterpret_cast<uint32_t*>(&lo);
    p.y = *reinterpret_cast<uint32_t*>(&hi);
    ((uint2*)g_Ebf)[i] = p;
    float s = v.x * v.x + v.y * v.y + v.z * v.z + v.w * v.w;
    #pragma unroll
    for (int off = 16; off; off >>= 1) s += __shfl_xor_sync(0xffffffffu, s, off);
    if ((tid & 31) == 0) wsum[tid >> 5] = s;
    if (blockIdx.x < 4) g_counts[blockIdx.x * 256 + tid] = 0;
    __syncthreads();
    if (tid < 4) g_e2[blockIdx.x * 4 + tid] = wsum[2 * tid] + wsum[2 * tid + 1];
}

// inputs (B, D, T) -> g_Xf fp32 [n][d] + g_Xbf bf16 [n][d]
__global__ void k_transpose(const float* __restrict__ in) {
    __shared__ float tile[32][33];
    int b = blockIdx.z, d0 = blockIdx.y * 32, t0 = blockIdx.x * 32;
    int tx = threadIdx.x, ty = threadIdx.y;
    const float* src = in + ((size_t)b * D_ + d0) * T_ + t0;
    #pragma unroll
    for (int i = 0; i < 4; i++) tile[ty + 8 * i][tx] = src[(size_t)(ty + 8 * i) * T_ + tx];
    __syncthreads();
    float* dst = g_Xf + ((size_t)b * T_ + t0) * D_ + d0;
    #pragma unroll
    for (int i = 0; i < 4; i++) dst[(size_t)(ty + 8 * i) * D_ + tx] = tile[tx][ty + 8 * i];
    if (tx < 16) {
        #pragma unroll
        for (int i = 0; i < 4; i++) {
            int t = ty + 8 * i;
            __nv_bfloat162 h = __floats2bfloat162_rn(tile[2 * tx][t], tile[2 * tx + 1][t]);
            *reinterpret_cast<uint32_t*>(g_Xbf + ((size_t)(b * T_ + t0 + t)) * D_ + d0 + 2 * tx)
                = *reinterpret_cast<uint32_t*>(&h);
        }
    }
}

// ---------------- main: mma scores + online candidates + exact refine ----------------
__global__ void __launch_bounds__(256, 2) k_main(const float* __restrict__ embed) {
    extern __shared__ char sm[];
    char* Xs = sm;                                   // 128 rows x LDB
    char* Es = sm + 128 * LDB;                       // 2 x CH x LDB
    float*    e2s     = (float*)(sm + 128 * LDB + 2 * CH * LDB);   // 1024 floats
    unsigned* rowminU = (unsigned*)(e2s + K_);                     // 128
    int*      cnt     = (int*)(rowminU + 128);                     // 128
    unsigned* list    = (unsigned*)(cnt + 128);                    // 128*CMAX

    const int tid  = threadIdx.x;
    const int Nbase = blockIdx.x * 128;
    const int lane = tid & 31, w = tid >> 5;
    const int wm = w & 3, wn = w >> 2;
    const int g = lane >> 2, tg = lane & 3;

    const uint32_t XsA  = (uint32_t)__cvta_generic_to_shared(Xs);
    const uint32_t EsA0 = (uint32_t)__cvta_generic_to_shared(Es);
    const uint32_t EsA1 = EsA0 + CH * LDB;

    // ---- prologue: async X tile + E0 + E1 ----
    {
        const __nv_bfloat16* src = g_Xbf + (size_t)Nbase * D_;
        #pragma unroll
        for (int i = 0; i < 16; i++) {
            int j = tid + i * 256, row = j >> 5, u = j & 31;
            cp16(XsA + row * LDB + u * 16, src + (size_t)row * D_ + u * 8);
        }
        const __nv_bfloat16* es = g_Ebf;
        #pragma unroll
        for (int i = 0; i < 4; i++) {
            int j = tid + i * 256, row = j >> 5, u = j & 31;
            cp16(EsA0 + row * LDB + u * 16, es + (size_t)row * D_ + u * 8);
        }
        asm volatile("cp.async.commit_group;");
        es = g_Ebf + CH * D_;
        #pragma unroll
        for (int i = 0; i < 4; i++) {
            int j = tid + i * 256, row = j >> 5, u = j & 31;
            cp16(EsA1 + row * LDB + u * 16, es + (size_t)row * D_ + u * 8);
        }
        asm volatile("cp.async.commit_group;");
    }
    // e2 table + per-row state init (overlaps cp.async)
    ((float4*)e2s)[tid] = ((const float4*)g_e2)[tid];
    if (tid < 128) { rowminU[tid] = 0xFFFFFFFFu; cnt[tid] = 0; }

    const uint32_t aAddr = XsA + (uint32_t)((wm * 32 + (lane & 15)) * LDB + (lane >> 4) * 16);
    const uint32_t bOff  = (uint32_t)((wn * 16 + (lane & 15)) * LDB + (lane >> 4) * 16);

    #pragma unroll 1
    for (int c = 0; c < NCHUNK; c++) {
        if (c == NCHUNK - 1) { asm volatile("cp.async.wait_group 0;" ::: "memory"); }
        else                 { asm volatile("cp.async.wait_group 1;" ::: "memory"); }
        __syncthreads();

        const uint32_t bAddr = ((c & 1) ? EsA1 : EsA0) + bOff;

        float acc[2][2][4];
        #pragma unroll
        for (int tm = 0; tm < 2; tm++)
            #pragma unroll
            for (int tn = 0; tn < 2; tn++)
                #pragma unroll
                for (int q = 0; q < 4; q++) acc[tm][tn][q] = 0.f;

        #pragma unroll
        for (int ks = 0; ks < 16; ks++) {
            uint32_t a0[4], a1[4], b0[4];
            ldsm4(a0, aAddr + ks * 32);
            ldsm4(a1, aAddr + 16 * LDB + ks * 32);
            ldsm4(b0, bAddr + ks * 32);
            mma16816(acc[0][0], a0, b0[0], b0[2]);
            mma16816(acc[0][1], a0, b0[1], b0[3]);
            mma16816(acc[1][0], a1, b0[0], b0[2]);
            mma16816(acc[1][1], a1, b0[1], b0[3]);
        }

        // scores + running row-min
        float lmin[4] = {FLT_MAX, FLT_MAX, FLT_MAX, FLT_MAX};
        #pragma unroll
        for (int tm = 0; tm < 2; tm++) {
            #pragma unroll
            for (int tn = 0; tn < 2; tn++) {
                int kc = c * CH + wn * 16 + tn * 8 + tg * 2;
                float e20 = e2s[kc], e21 = e2s[kc + 1];
                acc[tm][tn][0] = fmaf(-2.f, acc[tm][tn][0], e20);
                acc[tm][tn][1] = fmaf(-2.f, acc[tm][tn][1], e21);
                acc[tm][tn][2] = fmaf(-2.f, acc[tm][tn][2], e20);
                acc[tm][tn][3] = fmaf(-2.f, acc[tm][tn][3], e21);
                lmin[tm * 2 + 0] = fminf(lmin[tm * 2 + 0], fminf(acc[tm][tn][0], acc[tm][tn][1]));
                lmin[tm * 2 + 1] = fminf(lmin[tm * 2 + 1], fminf(acc[tm][tn][2], acc[tm][tn][3]));
            }
        }
        #pragma unroll
        for (int s = 0; s < 4; s++) {
            float v = lmin[s];
            v = fminf(v, __shfl_xor_sync(0xffffffffu, v, 1));
            v = fminf(v, __shfl_xor_sync(0xffffffffu, v, 2));
            if (tg == 0) {
                int row = wm * 32 + (s >> 1) * 16 + (s & 1) * 8 + g;
                atomicMin(&rowminU[row], fkey(v));
            }
        }
        __syncthreads();

        // prefetch chunk c+2 into the buffer we just finished reading
        if (c + 2 < NCHUNK) {
            uint32_t dstA = (c & 1) ? EsA1 : EsA0;
            const __nv_bfloat16* es = g_Ebf + (size_t)(c + 2) * CH * D_;
            #pragma unroll
            for (int i = 0; i < 4; i++) {
                int j = tid + i * 256, row = j >> 5, u = j & 31;
                cp16(dstA + row * LDB + u * 16, es + (size_t)row * D_ + u * 8);
            }
            asm volatile("cp.async.commit_group;");
        }

        // candidate collection vs current row minima + MARGIN
        float thr[4];
        #pragma unroll
        for (int s = 0; s < 4; s++) {
            int row = wm * 32 + (s >> 1) * 16 + (s & 1) * 8 + g;
            thr[s] = fdecode(rowminU[row]) + MARGIN;
        }
        #pragma unroll
        for (int tm = 0; tm < 2; tm++)
            #pragma unroll
            for (int tn = 0; tn < 2; tn++)
                #pragma unroll
                for (int q = 0; q < 4; q++) {
                    float sc = acc[tm][tn][q];
                    int slot = tm * 2 + (q >> 1);
                    if (sc <= thr[slot]) {
                        int row = wm * 32 + tm * 16 + (q >> 1) * 8 + g;
                        int kk  = c * CH + wn * 16 + tn * 8 + tg * 2 + (q & 1);
                        int pos = atomicAdd(&cnt[row], 1);
                        if (pos < CMAX)
                            list[row * CMAX + pos] =
                                ((unsigned)kk << 16) |
                                (unsigned)__half_as_ushort(__float2half_rn(sc));
                    }
                }
    }
    __syncthreads();

    // ---- exact refine: warp w owns rows [w*16, w*16+16) ----
    for (int rr = 0; rr < 16; rr++) {
        int row = w * 16 + rr;
        size_t n = (size_t)Nbase + row;
        float rmn = fdecode(rowminU[row]);
        int c_ = cnt[row];
        const float4* xr = (const float4*)(g_Xf + n * D_);
        float4 xv0 = xr[lane * 2], xv1 = xr[lane * 2 + 1];
        float bestd = FLT_MAX; int bestk = 0;
        if (c_ <= CMAX) {
            float thr = rmn + MARGIN + 0.5f;   // + half-precision storage slack
            unsigned e = (lane < c_) ? list[row * CMAX + lane] : 0u;
            float sh = (lane < c_)
                ? __half2float(__ushort_as_half((unsigned short)(e & 0xFFFFu))) : FLT_MAX;
            unsigned mk = __ballot_sync(0xffffffffu, sh <= thr);
            while (mk) {
                int j = __ffs(mk) - 1; mk &= mk - 1;
                int kc = (int)(__shfl_sync(0xffffffffu, e, j) >> 16);
                float part = dist2(xv0, xv1, embed + (size_t)kc * D_, lane);
                if (part < bestd || (part == bestd && kc < bestk)) { bestd = part; bestk = kc; }
            }
        } else {
            // overflow fallback (statistically ~never): exact scan of all codewords
            for (int kc = 0; kc < K_; kc++) {
                float part = dist2(xv0, xv1, embed + (size_t)kc * D_, lane);
                if (part < bestd) { bestd = part; bestk = kc; }
            }
        }
        if (lane == 0) {
            g_qidx[n] = bestk;
            g_qd2[n]  = bestd;
            atomicAdd(&g_counts[bestk], 1);
        }
    }
}

// ---------------- z_q gather back to (B, D, T) ----------------
__global__ void k_gather(const float* __restrict__ embed, float* __restrict__ out, int out_size) {
    __shared__ int kk[32];
    __shared__ float tile[32][257];
    if (out_size < Z_) return;
    int b  = blockIdx.x >> 7;
    int t0 = (blockIdx.x & 127) << 5;
    int tid = threadIdx.x;
    if (tid < 32) kk[tid] = g_qidx[(b << 12) + t0 + tid];
    __syncthreads();
    int w = tid >> 5, lane = tid & 31;
    #pragma unroll
    for (int r = w; r < 32; r += 8) {
        const float4* er = (const float4*)(embed + (size_t)kk[r] * D_);
        float4 v0 = er[lane * 2], v1 = er[lane * 2 + 1];
        float* trow = &tile[r][lane * 8];
        trow[0] = v0.x; trow[1] = v0.y; trow[2] = v0.z; trow[3] = v0.w;
        trow[4] = v1.x; trow[5] = v1.y; trow[6] = v1.z; trow[7] = v1.w;
    }
    __syncthreads();
    int tt = tid & 31;
    int dh = tid >> 5;
    float* obase = out + ((size_t)b * D_) * T_ + t0 + tt;
    #pragma unroll
    for (int dp = 0; dp < 32; dp++) {
        int d = dp * 8 + dh;
        obase[(size_t)d * T_] = tile[tt][d];
    }
}

// ---------------- scalars: loss, kldiv (constant), perplexity ----------------
__global__ void k_final(float* __restrict__ out, int out_size) {
    __shared__ float sh[1024], sd[1024];
    int tid = threadIdx.x;
    float p = (float)g_counts[tid] * (1.0f / 65536.0f);
    sh[tid] = -p * logf(p + 1e-10f);
    float ds = 0.f;
    #pragma unroll 8
    for (int i = 0; i < 64; i++) ds += g_qd2[tid + i * 1024];
    sd[tid] = ds;
    __syncthreads();
    for (int s = 512; s; s >>= 1) {
        if (tid < s) { sh[tid] += sh[tid + s]; sd[tid] += sd[tid + s]; }
        __syncthreads();
    }
    if (tid == 0 && out_size >= Z_ + 18) {
        out[Z_] = 1.25f * sd[0] * (1.0f / 16777216.0f);
        float kld = (float)(6.931471805599453 * 4096.0);  // log(1024) * T
        #pragma unroll
        for (int i = 0; i < 16; i++) out[Z_ + 1 + i] = kld;
        out[Z_ + 17] = expf(sh[0]);
    }
}

extern "C" void kernel_launch(void* const* d_in, const int* in_sizes, int n_in,
                              void* d_out, int out_size) {
    const float* inputs = (const float*)d_in[0];
    const float* embed  = (const float*)d_in[1];
    float* out = (float*)d_out;

    const int SMEM = 128 * LDB + 2 * CH * LDB + K_ * 4 + 128 * 4 + 128 * 4 + 128 * CMAX * 4; // 114688 B
    cudaFuncSetAttribute(k_main, cudaFuncAttributeMaxDynamicSharedMemorySize, SMEM);

    k_prep<<<256, 256>>>(embed);
    k_transpose<<<dim3(T_ / 32, D_ / 32, B_), dim3(32, 8)>>>(inputs);
    k_main<<<N_ / 128, 256, SMEM>>>(embed);
    k_gather<<<(B_ * T_) / 32, 256>>>(embed, out, out_size);
    k_final<<<1, 1024>>>(out, out_size);
}

// round 4
// speedup vs baseline: 2.5350x; 1.0365x over previous
#include <cuda_runtime.h>
#include <cuda_bf16.h>
#include <cuda_fp16.h>
#include <cstdint>
#include <cfloat>
#include <math.h>

#define B_  16
#define D_  256
#define T_  4096
#define N_  65536                  // B_*T_
#define K_  1024
#define Z_  16777216               // N_*D_

#define CH      32                 // codewords per chunk
#define NCHUNK  (K_/CH)            // 32
#define LDB     528                // padded smem row stride in BYTES (33 x 16B, odd -> conflict-free ldmatrix)
#define CMAX    16                 // candidate list capacity per row
#define MARGIN  1.0f

// ---------------- scratch (static device memory) ----------------
__device__ __align__(16) float          g_Xf [N_ * D_];   // 64MB fp32 transposed inputs [n][d]
__device__ __align__(16) __nv_bfloat16  g_Xbf[N_ * D_];   // 32MB bf16 transposed inputs
__device__ __align__(16) __nv_bfloat16  g_Ebf[K_ * D_];   // 512KB bf16 codebook
__device__ __align__(16) float g_e2[K_];
__device__ int   g_qidx[N_];
__device__ float g_qd2[N_];
__device__ int   g_counts[K_];

// ---------------- helpers ----------------
__device__ __forceinline__ unsigned fkey(float f) {       // order-preserving float->uint
    unsigned u = __float_as_uint(f);
    return u ^ ((unsigned)((int)u >> 31) | 0x80000000u);
}
__device__ __forceinline__ float fdecode(unsigned u) {
    unsigned m = (u >> 31) ? 0x80000000u : 0xFFFFFFFFu;
    return __uint_as_float(u ^ m);
}
__device__ __forceinline__ void cp16(uint32_t dst, const void* src) {
    asm volatile("cp.async.cg.shared.global [%0], [%1], 16;" :: "r"(dst), "l"(src));
}
__device__ __forceinline__ void ldsm4(uint32_t r[4], uint32_t addr) {
    asm volatile("ldmatrix.sync.aligned.m8n8.x4.shared.b16 {%0,%1,%2,%3}, [%4];"
                 : "=r"(r[0]), "=r"(r[1]), "=r"(r[2]), "=r"(r[3]) : "r"(addr));
}
__device__ __forceinline__ void mma16816(float c[4], const uint32_t a[4],
                                         uint32_t b0, uint32_t b1) {
    asm volatile(
        "mma.sync.aligned.m16n8k16.row.col.f32.bf16.bf16.f32 "
        "{%0,%1,%2,%3}, {%4,%5,%6,%7}, {%8,%9}, {%0,%1,%2,%3};"
        : "+f"(c[0]), "+f"(c[1]), "+f"(c[2]), "+f"(c[3])
        : "r"(a[0]), "r"(a[1]), "r"(a[2]), "r"(a[3]), "r"(b0), "r"(b1));
}
// exact fp32 distance, warp-cooperative
__device__ __forceinline__ float dist2(float4 xv0, float4 xv1, const float* e, int lane) {
    const float4* er = (const float4*)e;
    float4 ev0 = er[lane * 2], ev1 = er[lane * 2 + 1];
    float d0 = xv0.x - ev0.x, d1 = xv0.y - ev0.y, d2 = xv0.z - ev0.z, d3 = xv0.w - ev0.w;
    float part = d0 * d0 + d1 * d1 + d2 * d2 + d3 * d3;
    d0 = xv1.x - ev1.x; d1 = xv1.y - ev1.y; d2 = xv1.z - ev1.z; d3 = xv1.w - ev1.w;
    part += d0 * d0 + d1 * d1 + d2 * d2 + d3 * d3;
    #pragma unroll
    for (int off = 16; off; off >>= 1) part += __shfl_xor_sync(0xffffffffu, part, off);
    return part;
}

// ---------------- prep: counts=0, bf16 codebook, e2 ----------------
__global__ void k_prep(const float* __restrict__ embed) {
    __shared__ float wsum[8];
    int tid = threadIdx.x;
    int i = blockIdx.x * 256 + tid;                  // float4 index over K_*D_/4 = 65536
    float4 v = ((const float4*)embed)[i];
    __nv_bfloat162 lo = __floats2bfloat162_rn(v.x, v.y);
    __nv_bfloat162 hi = __floats2bfloat162_rn(v.z, v.w);
    uint2 p;
    p.x = *reinterpret_cast<uint32_t*>(&lo);
    p.y = *reinterpret_cast<uint32_t*>(&hi);
    ((uint2*)g_Ebf)[i] = p;
    float s = v.x * v.x + v.y * v.y + v.z * v.z + v.w * v.w;
    #pragma unroll
    for (int off = 16; off; off >>= 1) s += __shfl_xor_sync(0xffffffffu, s, off);
    if ((tid & 31) == 0) wsum[tid >> 5] = s;
    if (blockIdx.x < 4) g_counts[blockIdx.x * 256 + tid] = 0;
    __syncthreads();
    if (tid < 4) g_e2[blockIdx.x * 4 + tid] = wsum[2 * tid] + wsum[2 * tid + 1];
}

// inputs (B, D, T) -> g_Xf fp32 [n][d] + g_Xbf bf16 [n][d]
__global__ void k_transpose(const float* __restrict__ in) {
    __shared__ float tile[32][33];
    int b = blockIdx.z, d0 = blockIdx.y * 32, t0 = blockIdx.x * 32;
    int tx = threadIdx.x, ty = threadIdx.y;
    const float* src = in + ((size_t)b * D_ + d0) * T_ + t0;
    #pragma unroll
    for (int i = 0; i < 4; i++) tile[ty + 8 * i][tx] = src[(size_t)(ty + 8 * i) * T_ + tx];
    __syncthreads();
    float* dst = g_Xf + ((size_t)b * T_ + t0) * D_ + d0;
    #pragma unroll
    for (int i = 0; i < 4; i++) dst[(size_t)(ty + 8 * i) * D_ + tx] = tile[tx][ty + 8 * i];
    if (tx < 16) {
        #pragma unroll
        for (int i = 0; i < 4; i++) {
            int t = ty + 8 * i;
            __nv_bfloat162 h = __floats2bfloat162_rn(tile[2 * tx][t], tile[2 * tx + 1][t]);
            *reinterpret_cast<uint32_t*>(g_Xbf + ((size_t)(b * T_ + t0 + t)) * D_ + d0 + 2 * tx)
                = *reinterpret_cast<uint32_t*>(&h);
        }
    }
}

// ---------------- main: mma scores + online candidates + exact refine ----------------
__global__ void __launch_bounds__(256, 2) k_main(const float* __restrict__ embed) {
    extern __shared__ char sm[];
    char* Xs = sm;                                   // 128 rows x LDB
    char* Es = sm + 128 * LDB;                       // 2 x CH x LDB
    float*    e2s     = (float*)(sm + 128 * LDB + 2 * CH * LDB);   // 1024 floats
    unsigned* rowminU = (unsigned*)(e2s + K_);                     // 128
    int*      cnt     = (int*)(rowminU + 128);                     // 128
    unsigned* list    = (unsigned*)(cnt + 128);                    // 128*CMAX

    const int tid  = threadIdx.x;
    const int Nbase = blockIdx.x * 128;
    const int lane = tid & 31, w = tid >> 5;
    const int wm = w & 3, wn = w >> 2;
    const int g = lane >> 2, tg = lane & 3;

    const uint32_t XsA  = (uint32_t)__cvta_generic_to_shared(Xs);
    const uint32_t EsA0 = (uint32_t)__cvta_generic_to_shared(Es);
    const uint32_t EsA1 = EsA0 + CH * LDB;

    // ---- prologue: group A = X tile + E0 ; group B = E1 ----
    {
        const __nv_bfloat16* src = g_Xbf + (size_t)Nbase * D_;
        #pragma unroll
        for (int i = 0; i < 16; i++) {
            int j = tid + i * 256, row = j >> 5, u = j & 31;
            cp16(XsA + row * LDB + u * 16, src + (size_t)row * D_ + u * 8);
        }
        const __nv_bfloat16* es = g_Ebf;
        #pragma unroll
        for (int i = 0; i < 4; i++) {
            int j = tid + i * 256, row = j >> 5, u = j & 31;
            cp16(EsA0 + row * LDB + u * 16, es + (size_t)row * D_ + u * 8);
        }
        asm volatile("cp.async.commit_group;");
        es = g_Ebf + CH * D_;
        #pragma unroll
        for (int i = 0; i < 4; i++) {
            int j = tid + i * 256, row = j >> 5, u = j & 31;
            cp16(EsA1 + row * LDB + u * 16, es + (size_t)row * D_ + u * 8);
        }
        asm volatile("cp.async.commit_group;");
    }
    // e2 table + per-row state init (overlaps cp.async)
    ((float4*)e2s)[tid] = ((const float4*)g_e2)[tid];
    if (tid < 128) { rowminU[tid] = 0xFFFFFFFFu; cnt[tid] = 0; }

    const uint32_t aAddr = XsA + (uint32_t)((wm * 32 + (lane & 15)) * LDB + (lane >> 4) * 16);
    const uint32_t bOff  = (uint32_t)((wn * 16 + (lane & 15)) * LDB + (lane >> 4) * 16);

    #pragma unroll 1
    for (int c = 0; c < NCHUNK; c++) {
        if (c == 0) { asm volatile("cp.async.wait_group 1;" ::: "memory"); }
        else        { asm volatile("cp.async.wait_group 0;" ::: "memory"); }
        __syncthreads();   // buffer (c+1)&1 free (last read in chunk c-1) + chunk c's E landed

        // prefetch chunk c+1 into its buffer (full chunk of time to land)
        if (c >= 1 && c + 1 < NCHUNK) {
            uint32_t dstA = ((c + 1) & 1) ? EsA1 : EsA0;
            const __nv_bfloat16* es = g_Ebf + (size_t)(c + 1) * CH * D_;
            #pragma unroll
            for (int i = 0; i < 4; i++) {
                int j = tid + i * 256, row = j >> 5, u = j & 31;
                cp16(dstA + row * LDB + u * 16, es + (size_t)row * D_ + u * 8);
            }
            asm volatile("cp.async.commit_group;");
        }

        const uint32_t bAddr = ((c & 1) ? EsA1 : EsA0) + bOff;

        float acc[2][2][4];
        #pragma unroll
        for (int tm = 0; tm < 2; tm++)
            #pragma unroll
            for (int tn = 0; tn < 2; tn++)
                #pragma unroll
                for (int q = 0; q < 4; q++) acc[tm][tn][q] = 0.f;

        #pragma unroll
        for (int ks = 0; ks < 16; ks++) {
            uint32_t a0[4], a1[4], b0[4];
            ldsm4(a0, aAddr + ks * 32);
            ldsm4(a1, aAddr + 16 * LDB + ks * 32);
            ldsm4(b0, bAddr + ks * 32);
            mma16816(acc[0][0], a0, b0[0], b0[2]);
            mma16816(acc[0][1], a0, b0[1], b0[3]);
            mma16816(acc[1][0], a1, b0[0], b0[2]);
            mma16816(acc[1][1], a1, b0[1], b0[3]);
        }

        // scores + running row-min
        float lmin[4] = {FLT_MAX, FLT_MAX, FLT_MAX, FLT_MAX};
        #pragma unroll
        for (int tm = 0; tm < 2; tm++) {
            #pragma unroll
            for (int tn = 0; tn < 2; tn++) {
                int kc = c * CH + wn * 16 + tn * 8 + tg * 2;
                float e20 = e2s[kc], e21 = e2s[kc + 1];
                acc[tm][tn][0] = fmaf(-2.f, acc[tm][tn][0], e20);
                acc[tm][tn][1] = fmaf(-2.f, acc[tm][tn][1], e21);
                acc[tm][tn][2] = fmaf(-2.f, acc[tm][tn][2], e20);
                acc[tm][tn][3] = fmaf(-2.f, acc[tm][tn][3], e21);
                lmin[tm * 2 + 0] = fminf(lmin[tm * 2 + 0], fminf(acc[tm][tn][0], acc[tm][tn][1]));
                lmin[tm * 2 + 1] = fminf(lmin[tm * 2 + 1], fminf(acc[tm][tn][2], acc[tm][tn][3]));
            }
        }
        #pragma unroll
        for (int s = 0; s < 4; s++) {
            float v = lmin[s];
            v = fminf(v, __shfl_xor_sync(0xffffffffu, v, 1));
            v = fminf(v, __shfl_xor_sync(0xffffffffu, v, 2));
            if (tg == 0) {
                int row = wm * 32 + (s >> 1) * 16 + (s & 1) * 8 + g;
                atomicMin(&rowminU[row], fkey(v));
            }
        }
        // chunk 0 needs a converged min (else +inf threshold floods the list);
        // for c>=1 a stale min is provably safe (stale >= global min).
        if (c == 0) __syncthreads();

        // candidate collection vs current (possibly stale) row minima + MARGIN
        float thr[4];
        #pragma unroll
        for (int s = 0; s < 4; s++) {
            int row = wm * 32 + (s >> 1) * 16 + (s & 1) * 8 + g;
            thr[s] = fdecode(rowminU[row]) + MARGIN;
        }
        #pragma unroll
        for (int tm = 0; tm < 2; tm++)
            #pragma unroll
            for (int tn = 0; tn < 2; tn++)
                #pragma unroll
                for (int q = 0; q < 4; q++) {
                    float sc = acc[tm][tn][q];
                    int slot = tm * 2 + (q >> 1);
                    if (sc <= thr[slot]) {
                        int row = wm * 32 + tm * 16 + (q >> 1) * 8 + g;
                        int kk  = c * CH + wn * 16 + tn * 8 + tg * 2 + (q & 1);
                        int pos = atomicAdd(&cnt[row], 1);
                        if (pos < CMAX)
                            list[row * CMAX + pos] =
                                ((unsigned)kk << 16) |
                                (unsigned)__half_as_ushort(__float2half_rn(sc));
                    }
                }
    }
    __syncthreads();

    // ---- exact refine: warp w owns rows [w*16, w*16+16) ----
    for (int rr = 0; rr < 16; rr++) {
        int row = w * 16 + rr;
        size_t n = (size_t)Nbase + row;
        float rmn = fdecode(rowminU[row]);
        int c_ = cnt[row];
        const float4* xr = (const float4*)(g_Xf + n * D_);
        float4 xv0 = xr[lane * 2], xv1 = xr[lane * 2 + 1];
        float bestd = FLT_MAX; int bestk = 0;
        if (c_ <= CMAX) {
            float thr = rmn + MARGIN + 0.5f;   // + half-precision storage slack
            unsigned e = (lane < c_) ? list[row * CMAX + lane] : 0u;
            float sh = (lane < c_)
                ? __half2float(__ushort_as_half((unsigned short)(e & 0xFFFFu))) : FLT_MAX;
            unsigned mk = __ballot_sync(0xffffffffu, sh <= thr);
            while (mk) {
                int j = __ffs(mk) - 1; mk &= mk - 1;
                int kc = (int)(__shfl_sync(0xffffffffu, e, j) >> 16);
                float part = dist2(xv0, xv1, embed + (size_t)kc * D_, lane);
                if (part < bestd || (part == bestd && kc < bestk)) { bestd = part; bestk = kc; }
            }
        } else {
            // overflow fallback (statistically ~never): exact scan of all codewords
            for (int kc = 0; kc < K_; kc++) {
                float part = dist2(xv0, xv1, embed + (size_t)kc * D_, lane);
                if (part < bestd) { bestd = part; bestk = kc; }
            }
        }
        if (lane == 0) {
            g_qidx[n] = bestk;
            g_qd2[n]  = bestd;
            atomicAdd(&g_counts[bestk], 1);
        }
    }
}

// ---------------- z_q gather back to (B, D, T): lane-per-t, no smem ----------------
// lane l owns t = t0 + l: scattered L2-hot float4 reads of its codeword row,
// perfectly coalesced 128B stores along t for every d.
__global__ void __launch_bounds__(256) k_gather(const float* __restrict__ embed,
                                                float* __restrict__ out, int out_size) {
    if (out_size < Z_) return;
    int lane = threadIdx.x & 31, w = threadIdx.x >> 5;
    int n0 = blockIdx.x * 256 + w * 32;             // 8 warps x 32 t per block
    int b  = n0 >> 12;                              // n0 / T_
    int t  = (n0 & (T_ - 1)) + lane;
    int kt = g_qidx[n0 + lane];
    const float4* er = (const float4*)(embed + (size_t)kt * D_);
    float* ob = out + (size_t)b * D_ * T_ + t;
    #pragma unroll 4
    for (int d4 = 0; d4 < D_ / 4; d4++) {
        float4 v = er[d4];
        int d = d4 * 4;
        ob[(size_t)d * T_]       = v.x;
        ob[(size_t)(d + 1) * T_] = v.y;
        ob[(size_t)(d + 2) * T_] = v.z;
        ob[(size_t)(d + 3) * T_] = v.w;
    }
}

// ---------------- scalars: loss, kldiv (constant), perplexity ----------------
__global__ void k_final(float* __restrict__ out, int out_size) {
    __shared__ float sh[1024], sd[1024];
    int tid = threadIdx.x;
    float p = (float)g_counts[tid] * (1.0f / 65536.0f);
    sh[tid] = -p * logf(p + 1e-10f);
    float ds = 0.f;
    #pragma unroll 8
    for (int i = 0; i < 64; i++) ds += g_qd2[tid + i * 1024];
    sd[tid] = ds;
    __syncthreads();
    for (int s = 512; s; s >>= 1) {
        if (tid < s) { sh[tid] += sh[tid + s]; sd[tid] += sd[tid + s]; }
        __syncthreads();
    }
    if (tid == 0 && out_size >= Z_ + 18) {
        out[Z_] = 1.25f * sd[0] * (1.0f / 16777216.0f);
        float kld = (float)(6.931471805599453 * 4096.0);  // log(1024) * T
        #pragma unroll
        for (int i = 0; i < 16; i++) out[Z_ + 1 + i] = kld;
        out[Z_ + 17] = expf(sh[0]);
    }
}

extern "C" void kernel_launch(void* const* d_in, const int* in_sizes, int n_in,
                              void* d_out, int out_size) {
    const float* inputs = (const float*)d_in[0];
    const float* embed  = (const float*)d_in[1];
    float* out = (float*)d_out;

    const int SMEM = 128 * LDB + 2 * CH * LDB + K_ * 4 + 128 * 4 + 128 * 4 + 128 * CMAX * 4; // 114688 B
    cudaFuncSetAttribute(k_main, cudaFuncAttributeMaxDynamicSharedMemorySize, SMEM);

    k_prep<<<256, 256>>>(embed);
    k_transpose<<<dim3(T_ / 32, D_ / 32, B_), dim3(32, 8)>>>(inputs);
    k_main<<<N_ / 128, 256, SMEM>>>(embed);
    k_gather<<<N_ / 256, 256>>>(embed, out, out_size);
    k_final<<<1, 1024>>>(out, out_size);
}